// round 1
// baseline (speedup 1.0000x reference)
#include <cuda_runtime.h>
#include <cuda_bf16.h>

// Problem constants
#define DIM   96
#define NBIN  64            // 8 theta * 8 phi
#define BSZ   15            // sliding window
#define NVOX  (DIM*DIM*DIM)             // 884736
#define NFLT  ((size_t)NVOX * NBIN)     // 56,623,104 floats
#define NQ4   (NVOX * 16)               // float4 count = 14,155,776
#define LINE4 (DIM * 16)                // 1536 float4 per (z,y) row
#define PLANE4 (DIM * DIM * 16)         // 147456 float4 per z-plane

// 226.5 MB scratch (static device allocation — allowed)
__device__ float g_buf[NFLT];

// ---------------------------------------------------------------------------
// Stage 1: gradients -> soft binning -> dense V[z][y][x][64]
// Each thread owns one voxel; 4 (bin, weight) pairs go to shared memory, then
// a cooperative coalesced write phase emits 16 float4 per voxel.
// ---------------------------------------------------------------------------
__global__ void __launch_bounds__(256) bin_kernel(const float* __restrict__ x)
{
    __shared__ int   sb[256 * 4];
    __shared__ float sv[256 * 4];

    const int tid = threadIdx.x;
    const int v   = blockIdx.x * 256 + tid;     // voxel id, grid sized exactly

    const int xi  = v % DIM;
    const int rem = v / DIM;
    const int yi  = rem % DIM;
    const int zi  = rem / DIM;

    // central differences with zero padding (conv3d pad=1)
    const float xp = (xi < DIM - 1) ? x[v + 1]        : 0.f;
    const float xm = (xi > 0)       ? x[v - 1]        : 0.f;
    const float yp = (yi < DIM - 1) ? x[v + DIM]      : 0.f;
    const float ym = (yi > 0)       ? x[v - DIM]      : 0.f;
    const float zp = (zi < DIM - 1) ? x[v + DIM*DIM]  : 0.f;
    const float zm = (zi > 0)       ? x[v - DIM*DIM]  : 0.f;
    const float gx = xp - xm;
    const float gy = yp - ym;
    const float gz = zp - zm;

    const float EPS    = 2.2204460492503131e-16f;
    const float TWO_PI = (float)(2.0 * 3.14159265358979323846);  // fp32(2*pi)
    const float PI_F   = (float)(3.14159265358979323846);        // fp32(pi)
    const float TSTEP  = TWO_PI / 8.0f;   // exact /8
    const float PSTEP  = PI_F   / 8.0f;   // exact /8

    const float r     = sqrtf(gx*gx + gy*gy + gz*gz);
    float       theta = atanf(gy / (gx + EPS));
    const float phi   = acosf(gz / (r + EPS));
    if (theta < 0.f) theta += TWO_PI;

    const float t_raw = theta / TSTEP;
    const float p_raw = phi   / PSTEP;

    const float ft = floorf(t_raw);
    int lt = (int)ft;            if (lt == 8) lt = 0;
    int lp = (int)floorf(p_raw); if (lp == 8) lp = 0;
    const int ht = (lt + 1) & 7;
    const int hp = (lp + 1) & 7;

    // NOTE: theta fractional part intentionally reused for phi ratios
    // (faithful to the reference's bug).
    const float frac  = t_raw - ft;
    const float w_lo  = fminf(frac, 1.0f - frac);
    const float w_hi  = 1.0f - w_lo;
    const float wp_lo = (frac == 0.0f) ? 1.0f : w_lo;
    const float wp_hi = 1.0f - wp_lo;

    sb[tid*4 + 0] = lt*8 + lp;  sv[tid*4 + 0] = r * w_lo * wp_lo;
    sb[tid*4 + 1] = ht*8 + lp;  sv[tid*4 + 1] = r * w_hi * wp_lo;
    sb[tid*4 + 2] = lt*8 + hp;  sv[tid*4 + 2] = r * w_lo * wp_hi;
    sb[tid*4 + 3] = ht*8 + hp;  sv[tid*4 + 3] = r * w_hi * wp_hi;
    __syncthreads();

    // coalesced write: block covers 256 voxels * 16 float4 = 4096 float4
    float4* out4 = reinterpret_cast<float4*>(g_buf) + (size_t)blockIdx.x * 4096;
    #pragma unroll
    for (int k = 0; k < 16; k++) {
        const int j  = tid + k * 256;   // 0..4095
        const int lv = j >> 4;          // local voxel
        const int g4 = (j & 15) * 4;    // first bin of this float4
        float4 o = make_float4(0.f, 0.f, 0.f, 0.f);
        #pragma unroll
        for (int c = 0; c < 4; c++) {
            const int   d   = sb[lv*4 + c] - g4;
            const float val = sv[lv*4 + c];
            o.x += (d == 0) ? val : 0.f;
            o.y += (d == 1) ? val : 0.f;
            o.z += (d == 2) ? val : 0.f;
            o.w += (d == 3) ? val : 0.f;
        }
        out4[j] = o;
    }
}

// ---------------------------------------------------------------------------
// Sliding-window sum of size 15, stride 1, zero beyond the end, along one axis.
// One thread per (line, float4-of-bins). AXIS: 0=X, 1=Y, 2=Z.
// ---------------------------------------------------------------------------
template <int AXIS>
__global__ void __launch_bounds__(256) slide_kernel(const float4* __restrict__ in,
                                                    float4* __restrict__ out)
{
    const int t = blockIdx.x * 256 + threadIdx.x;  // < 96*96*16, grid exact
    const int q = t & 15;
    const int l = t >> 4;

    int base, stride;
    if (AXIS == 0) {                       // along X, line = (z,y)
        base   = l * LINE4 + q;
        stride = 16;
    } else if (AXIS == 1) {                // along Y, line = (z,x)
        const int xi = l % DIM, zi = l / DIM;
        base   = zi * PLANE4 + xi * 16 + q;
        stride = LINE4;
    } else {                               // along Z, line = (y,x)
        const int xi = l % DIM, yi = l / DIM;
        base   = yi * LINE4 + xi * 16 + q;
        stride = PLANE4;
    }

    float4 s = make_float4(0.f, 0.f, 0.f, 0.f);
    #pragma unroll
    for (int j = 0; j < BSZ - 1; j++) {
        const float4 a = in[base + j * stride];
        s.x += a.x; s.y += a.y; s.z += a.z; s.w += a.w;
    }

    int off = base;
    #pragma unroll 4
    for (int i = 0; i < DIM; i++) {
        if (i + BSZ - 1 < DIM) {
            const float4 a = in[base + (i + BSZ - 1) * stride];
            s.x += a.x; s.y += a.y; s.z += a.z; s.w += a.w;
        }
        __stcs(&out[off], s);              // streaming store, keep input in L2
        const float4 b = in[off];          // trailing element (L2 hit)
        s.x -= b.x; s.y -= b.y; s.z -= b.z; s.w -= b.w;
        off += stride;
    }
}

// ---------------------------------------------------------------------------
extern "C" void kernel_launch(void* const* d_in, const int* in_sizes, int n_in,
                              void* d_out, int out_size)
{
    const float* x   = (const float*)d_in[0];
    float*       out = (float*)d_out;

    void* bufp = nullptr;
    cudaGetSymbolAddress(&bufp, g_buf);
    float4* buf4 = (float4*)bufp;
    float4* out4 = (float4*)out;

    const int binBlocks   = NVOX / 256;            // 3456
    const int slideBlocks = (DIM * DIM * 16) / 256; // 576

    bin_kernel<<<binBlocks, 256>>>(x);              // x -> g_buf
    slide_kernel<0><<<slideBlocks, 256>>>(buf4, out4);  // X: g_buf -> out
    slide_kernel<1><<<slideBlocks, 256>>>(out4, buf4);  // Y: out -> g_buf
    slide_kernel<2><<<slideBlocks, 256>>>(buf4, out4);  // Z: g_buf -> out
}

// round 2
// speedup vs baseline: 1.5691x; 1.5691x over previous
#include <cuda_runtime.h>
#include <cuda_fp16.h>

// Problem constants
#define DIM   96
#define NBIN  64              // 8 theta * 8 phi
#define BSZ   15              // sliding window
#define NVOX  (DIM*DIM*DIM)               // 884736
#define NFLT  ((size_t)NVOX * NBIN)       // 56,623,104
#define LINEH (DIM * NBIN)                // halves per (z,y) line = 6144
#define LINEU2  (DIM * NBIN / 4)          // uint2 (4 halves) per y-row = 1536
#define PLANEU2 (DIM * LINEU2)            // 147456

// two 113 MB fp16 scratch buffers (static device allocation — allowed)
__device__ __half g_h0[NFLT];
__device__ __half g_h1[NFLT];

__device__ __forceinline__ unsigned pack2(float a, float b) {
    __half2 h = __float22half2_rn(make_float2(a, b));
    return *reinterpret_cast<unsigned*>(&h);
}
__device__ __forceinline__ float2 unpack2(unsigned u) {
    __half2 h = *reinterpret_cast<__half2*>(&u);
    return __half22float2(h);
}

// ---------------------------------------------------------------------------
// Stage 1 (fused): gradients -> soft binning -> X sliding-sum -> fp16 line
// One block per (z,y) line. V line lives in smem; X-window via per-bin prefix.
// ---------------------------------------------------------------------------
__global__ void __launch_bounds__(128) binx_kernel(const float* __restrict__ x,
                                                   __half* __restrict__ V)
{
    __shared__ float Vs[DIM * NBIN];          // 24 KB  (later aliased as fp16 out)
    __shared__ float Ps[(DIM + 1) * NBIN];    // 24.25 KB inclusive-prefix (P[0]=0)

    const int tid  = threadIdx.x;
    const int line = blockIdx.x;              // 0..9215
    const int yi   = line % DIM;
    const int zi   = line / DIM;

    for (int i = tid; i < DIM * NBIN; i += 128) Vs[i] = 0.f;
    __syncthreads();

    if (tid < DIM) {
        const int xi = tid;
        const int v  = (zi * DIM + yi) * DIM + xi;

        const float xp = (xi < DIM - 1) ? x[v + 1]       : 0.f;
        const float xm = (xi > 0)       ? x[v - 1]       : 0.f;
        const float yp = (yi < DIM - 1) ? x[v + DIM]     : 0.f;
        const float ym = (yi > 0)       ? x[v - DIM]     : 0.f;
        const float zp = (zi < DIM - 1) ? x[v + DIM*DIM] : 0.f;
        const float zm = (zi > 0)       ? x[v - DIM*DIM] : 0.f;
        const float gx = xp - xm, gy = yp - ym, gz = zp - zm;

        const float EPS    = 2.2204460492503131e-16f;
        const float TWO_PI = (float)(2.0 * 3.14159265358979323846);
        const float PI_F   = (float)(3.14159265358979323846);
        const float TSTEP  = TWO_PI / 8.0f;
        const float PSTEP  = PI_F   / 8.0f;

        const float r   = sqrtf(gx*gx + gy*gy + gz*gz);
        float theta     = atanf(gy / (gx + EPS));
        const float phi = acosf(gz / (r + EPS));
        if (theta < 0.f) theta += TWO_PI;

        const float t_raw = theta / TSTEP;
        const float p_raw = phi   / PSTEP;

        const float ft = floorf(t_raw);
        int lt = (int)ft;            if (lt == 8) lt = 0;
        int lp = (int)floorf(p_raw); if (lp == 8) lp = 0;
        const int ht = (lt + 1) & 7;
        const int hp = (lp + 1) & 7;

        // theta frac intentionally reused for phi ratios (reference bug, faithful)
        const float frac  = t_raw - ft;
        const float w_lo  = fminf(frac, 1.0f - frac);
        const float w_hi  = 1.0f - w_lo;
        const float wp_lo = (frac == 0.0f) ? 1.0f : w_lo;
        const float wp_hi = 1.0f - wp_lo;

        float* row = &Vs[xi * NBIN];           // row exclusive to this thread
        row[lt*8 + lp] += r * w_lo * wp_lo;
        row[ht*8 + lp] += r * w_hi * wp_lo;
        row[lt*8 + hp] += r * w_lo * wp_hi;
        row[ht*8 + hp] += r * w_hi * wp_hi;
    }
    __syncthreads();

    // per-bin inclusive prefix along x (sequential per bin, 64 parallel bins)
    if (tid < NBIN) {
        const int b = tid;
        float s = 0.f;
        Ps[b] = 0.f;
        #pragma unroll 4
        for (int i = 0; i < DIM; i++) {
            s += Vs[i * NBIN + b];
            Ps[(i + 1) * NBIN + b] = s;
        }
    }
    __syncthreads();

    // Xsum(i,b) = P[min(i+15,96)] - P[i]  (zero beyond end), to fp16, alias Vs
    __half* Hs = reinterpret_cast<__half*>(Vs);
    for (int e = tid; e < DIM * NBIN; e += 128) {
        const int i = e >> 6, b = e & 63;
        int hi = i + BSZ; if (hi > DIM) hi = DIM;
        Hs[e] = __float2half_rn(Ps[hi * NBIN + b] - Ps[i * NBIN + b]);
    }
    __syncthreads();

    // coalesced 16B vector write of the 12 KB line
    uint4* dst = reinterpret_cast<uint4*>(V) + (size_t)line * (LINEH / 8);
    const uint4* src = reinterpret_cast<const uint4*>(Hs);
    for (int i = tid; i < LINEH / 8; i += 128) dst[i] = src[i];
}

// ---------------------------------------------------------------------------
// Stage 2: sliding sum along Y, fp16 -> fp16. One thread per (z,x,q4) column,
// 4 halves (uint2) per element, fp32 running accumulators.
// ---------------------------------------------------------------------------
__global__ void __launch_bounds__(256) slideY_kernel(const uint2* __restrict__ in,
                                                     uint2* __restrict__ out)
{
    const int t = blockIdx.x * 256 + threadIdx.x;   // < 96*96*16 (grid exact)
    const int q = t & 15;
    const int c = t >> 4;
    const int xi = c % DIM, zi = c / DIM;
    const int base   = zi * PLANEU2 + xi * 16 + q;
    const int stride = LINEU2;

    float s0 = 0.f, s1 = 0.f, s2 = 0.f, s3 = 0.f;
    #pragma unroll
    for (int j = 0; j < BSZ - 1; j++) {
        const uint2 u = in[base + j * stride];
        const float2 a = unpack2(u.x), b = unpack2(u.y);
        s0 += a.x; s1 += a.y; s2 += b.x; s3 += b.y;
    }

    int off = base;
    #pragma unroll 4
    for (int i = 0; i < DIM; i++) {
        if (i + BSZ - 1 < DIM) {
            const uint2 u = in[base + (i + BSZ - 1) * stride];
            const float2 a = unpack2(u.x), b = unpack2(u.y);
            s0 += a.x; s1 += a.y; s2 += b.x; s3 += b.y;
        }
        uint2 o; o.x = pack2(s0, s1); o.y = pack2(s2, s3);
        __stcs(&out[off], o);
        const uint2 u = in[off];                    // trailing (L2 hit)
        const float2 a = unpack2(u.x), b = unpack2(u.y);
        s0 -= a.x; s1 -= a.y; s2 -= b.x; s3 -= b.y;
        off += stride;
    }
}

// ---------------------------------------------------------------------------
// Stage 3: sliding sum along Z, fp16 -> fp32 (d_out). One thread per (y,x,q4).
// ---------------------------------------------------------------------------
__global__ void __launch_bounds__(256) slideZ_kernel(const uint2* __restrict__ in,
                                                     float4* __restrict__ out)
{
    const int t = blockIdx.x * 256 + threadIdx.x;   // < 96*96*16
    const int q = t & 15;
    const int c = t >> 4;
    const int xi = c % DIM, yi = c / DIM;
    const int base   = yi * LINEU2 + xi * 16 + q;
    const int stride = PLANEU2;

    float s0 = 0.f, s1 = 0.f, s2 = 0.f, s3 = 0.f;
    #pragma unroll
    for (int j = 0; j < BSZ - 1; j++) {
        const uint2 u = in[base + j * stride];
        const float2 a = unpack2(u.x), b = unpack2(u.y);
        s0 += a.x; s1 += a.y; s2 += b.x; s3 += b.y;
    }

    int off = base;
    #pragma unroll 4
    for (int i = 0; i < DIM; i++) {
        if (i + BSZ - 1 < DIM) {
            const uint2 u = in[base + (i + BSZ - 1) * stride];
            const float2 a = unpack2(u.x), b = unpack2(u.y);
            s0 += a.x; s1 += a.y; s2 += b.x; s3 += b.y;
        }
        // float4 index: (((i*96+yi)*96+xi)*64 + q*4) / 4
        __stcs(&out[((i * DIM + yi) * DIM + xi) * 16 + q],
               make_float4(s0, s1, s2, s3));
        const uint2 u = in[off];                    // trailing (L2 hit)
        const float2 a = unpack2(u.x), b = unpack2(u.y);
        s0 -= a.x; s1 -= a.y; s2 -= b.x; s3 -= b.y;
        off += stride;
    }
}

// ---------------------------------------------------------------------------
extern "C" void kernel_launch(void* const* d_in, const int* in_sizes, int n_in,
                              void* d_out, int out_size)
{
    const float* x = (const float*)d_in[0];

    void *p0 = nullptr, *p1 = nullptr;
    cudaGetSymbolAddress(&p0, g_h0);
    cudaGetSymbolAddress(&p1, g_h1);

    const int binBlocks   = DIM * DIM;                   // 9216 lines
    const int slideBlocks = (DIM * DIM * 16) / 256;      // 576

    binx_kernel<<<binBlocks, 128>>>(x, (__half*)p0);                         // x -> Xsum(h0)
    slideY_kernel<<<slideBlocks, 256>>>((const uint2*)p0, (uint2*)p1);       // h0 -> h1
    slideZ_kernel<<<slideBlocks, 256>>>((const uint2*)p1, (float4*)d_out);   // h1 -> out
}

// round 3
// speedup vs baseline: 2.1142x; 1.3474x over previous
#include <cuda_runtime.h>
#include <cuda_fp16.h>

// Problem constants
#define DIM   96
#define NBIN  64              // 8 theta * 8 phi
#define BSZ   15              // sliding window
#define NVOX  (DIM*DIM*DIM)               // 884736
#define NFLT  ((size_t)NVOX * NBIN)       // 56,623,104
#define LINEH (DIM * NBIN)                // halves per (z,y) line = 6144
#define LINEU2  (DIM * NBIN / 4)          // uint2 per y-row = 1536
#define PLANEU2 (DIM * LINEU2)            // 147456
#define VSTR  66                          // padded smem row stride (floats, even)

// two 113 MB fp16 scratch buffers (static device allocation — allowed)
__device__ __half g_h0[NFLT];
__device__ __half g_h1[NFLT];

__device__ __forceinline__ unsigned pack2(float a, float b) {
    __half2 h = __float22half2_rn(make_float2(a, b));
    return *reinterpret_cast<unsigned*>(&h);
}
__device__ __forceinline__ float2 unpack2(unsigned u) {
    __half2 h = *reinterpret_cast<__half2*>(&u);
    return __half22float2(h);
}

// ---------------------------------------------------------------------------
// Stage 1 (fused): gradients -> soft binning -> X sliding-window sum -> fp16
// One block (256 thr) per (z,y) line. Dense 96x64 histogram in smem; window
// sums via running accumulators, 8-way segmented along x, 2 bins per thread.
// ---------------------------------------------------------------------------
__global__ void __launch_bounds__(256) binx_kernel(const float* __restrict__ x,
                                                   __half* __restrict__ V)
{
    __shared__ float Vs[DIM * VSTR];      // 24.75 KB (padded rows)

    const int tid  = threadIdx.x;
    const int line = blockIdx.x;          // 0..9215
    const int yi   = line % DIM;
    const int zi   = line / DIM;

    // zero histogram
    for (int i = tid; i < DIM * VSTR; i += 256) Vs[i] = 0.f;
    __syncthreads();

    // binning: one thread per voxel on this line (threads 0..95)
    if (tid < DIM) {
        const int xi = tid;
        const int v  = (zi * DIM + yi) * DIM + xi;

        const float xp = (xi < DIM - 1) ? x[v + 1]       : 0.f;
        const float xm = (xi > 0)       ? x[v - 1]       : 0.f;
        const float yp = (yi < DIM - 1) ? x[v + DIM]     : 0.f;
        const float ym = (yi > 0)       ? x[v - DIM]     : 0.f;
        const float zp = (zi < DIM - 1) ? x[v + DIM*DIM] : 0.f;
        const float zm = (zi > 0)       ? x[v - DIM*DIM] : 0.f;
        const float gx = xp - xm, gy = yp - ym, gz = zp - zm;

        const float EPS    = 2.2204460492503131e-16f;
        const float TWO_PI = (float)(2.0 * 3.14159265358979323846);
        const float PI_F   = (float)(3.14159265358979323846);
        const float TSTEP  = TWO_PI / 8.0f;
        const float PSTEP  = PI_F   / 8.0f;

        const float r   = sqrtf(gx*gx + gy*gy + gz*gz);
        float theta     = atanf(gy / (gx + EPS));
        const float phi = acosf(gz / (r + EPS));
        if (theta < 0.f) theta += TWO_PI;

        const float t_raw = theta / TSTEP;
        const float p_raw = phi   / PSTEP;

        const float ft = floorf(t_raw);
        int lt = (int)ft;            if (lt == 8) lt = 0;
        int lp = (int)floorf(p_raw); if (lp == 8) lp = 0;
        const int ht = (lt + 1) & 7;
        const int hp = (lp + 1) & 7;

        // theta frac intentionally reused for phi ratios (reference bug, faithful)
        const float frac  = t_raw - ft;
        const float w_lo  = fminf(frac, 1.0f - frac);
        const float w_hi  = 1.0f - w_lo;
        const float wp_lo = (frac == 0.0f) ? 1.0f : w_lo;
        const float wp_hi = 1.0f - wp_lo;

        float* row = &Vs[xi * VSTR];          // row exclusive to this thread
        row[lt*8 + lp] += r * w_lo * wp_lo;
        row[ht*8 + lp] += r * w_hi * wp_lo;
        row[lt*8 + hp] += r * w_lo * wp_hi;
        row[ht*8 + hp] += r * w_hi * wp_hi;
    }
    __syncthreads();

    // running-window sums: thread = (bin-pair b, segment seg), 12 rows/segment.
    // window at i covers rows i..i+14 (rows >= 96 contribute zero).
    {
        const int b   = tid & 31;         // bins 2b, 2b+1
        const int seg = tid >> 5;         // 0..7
        const int i0  = seg * 12;

        float w0 = 0.f, w1 = 0.f;
        #pragma unroll
        for (int j = 0; j < BSZ - 1; j++) {            // rows i0..i0+13
            const int rr = i0 + j;
            if (rr < DIM) {
                const float2 a = *reinterpret_cast<const float2*>(&Vs[rr * VSTR + 2*b]);
                w0 += a.x; w1 += a.y;
            }
        }

        unsigned* outu = reinterpret_cast<unsigned*>(V + (size_t)line * LINEH);
        #pragma unroll
        for (int i = i0; i < i0 + 12; i++) {
            const int hi = i + BSZ - 1;
            if (hi < DIM) {
                const float2 a = *reinterpret_cast<const float2*>(&Vs[hi * VSTR + 2*b]);
                w0 += a.x; w1 += a.y;
            }
            outu[i * 32 + b] = pack2(w0, w1);          // coalesced 128B/warp
            const float2 s = *reinterpret_cast<const float2*>(&Vs[i * VSTR + 2*b]);
            w0 -= s.x; w1 -= s.y;
        }
    }
}

// ---------------------------------------------------------------------------
// Stage 2: sliding sum along Y, fp16 -> fp16. One thread per (z,x,q4) column.
// ---------------------------------------------------------------------------
__global__ void __launch_bounds__(256) slideY_kernel(const uint2* __restrict__ in,
                                                     uint2* __restrict__ out)
{
    const int t = blockIdx.x * 256 + threadIdx.x;   // < 96*96*16 (grid exact)
    const int q = t & 15;
    const int c = t >> 4;
    const int xi = c % DIM, zi = c / DIM;
    const int base   = zi * PLANEU2 + xi * 16 + q;
    const int stride = LINEU2;

    float s0 = 0.f, s1 = 0.f, s2 = 0.f, s3 = 0.f;
    #pragma unroll
    for (int j = 0; j < BSZ - 1; j++) {
        const uint2 u = in[base + j * stride];
        const float2 a = unpack2(u.x), b = unpack2(u.y);
        s0 += a.x; s1 += a.y; s2 += b.x; s3 += b.y;
    }

    int off = base;
    #pragma unroll 4
    for (int i = 0; i < DIM; i++) {
        if (i + BSZ - 1 < DIM) {
            const uint2 u = in[base + (i + BSZ - 1) * stride];
            const float2 a = unpack2(u.x), b = unpack2(u.y);
            s0 += a.x; s1 += a.y; s2 += b.x; s3 += b.y;
        }
        uint2 o; o.x = pack2(s0, s1); o.y = pack2(s2, s3);
        __stcs(&out[off], o);
        const uint2 u = in[off];                    // trailing (L2 hit)
        const float2 a = unpack2(u.x), b = unpack2(u.y);
        s0 -= a.x; s1 -= a.y; s2 -= b.x; s3 -= b.y;
        off += stride;
    }
}

// ---------------------------------------------------------------------------
// Stage 3: sliding sum along Z, fp16 -> fp32 (d_out). One thread per (y,x,q4).
// ---------------------------------------------------------------------------
__global__ void __launch_bounds__(256) slideZ_kernel(const uint2* __restrict__ in,
                                                     float4* __restrict__ out)
{
    const int t = blockIdx.x * 256 + threadIdx.x;   // < 96*96*16
    const int q = t & 15;
    const int c = t >> 4;
    const int xi = c % DIM, yi = c / DIM;
    const int base   = yi * LINEU2 + xi * 16 + q;
    const int stride = PLANEU2;

    float s0 = 0.f, s1 = 0.f, s2 = 0.f, s3 = 0.f;
    #pragma unroll
    for (int j = 0; j < BSZ - 1; j++) {
        const uint2 u = in[base + j * stride];
        const float2 a = unpack2(u.x), b = unpack2(u.y);
        s0 += a.x; s1 += a.y; s2 += b.x; s3 += b.y;
    }

    int off = base;
    #pragma unroll 4
    for (int i = 0; i < DIM; i++) {
        if (i + BSZ - 1 < DIM) {
            const uint2 u = in[base + (i + BSZ - 1) * stride];
            const float2 a = unpack2(u.x), b = unpack2(u.y);
            s0 += a.x; s1 += a.y; s2 += b.x; s3 += b.y;
        }
        __stcs(&out[((i * DIM + yi) * DIM + xi) * 16 + q],
               make_float4(s0, s1, s2, s3));
        const uint2 u = in[off];                    // trailing (L2 hit)
        const float2 a = unpack2(u.x), b = unpack2(u.y);
        s0 -= a.x; s1 -= a.y; s2 -= b.x; s3 -= b.y;
        off += stride;
    }
}

// ---------------------------------------------------------------------------
extern "C" void kernel_launch(void* const* d_in, const int* in_sizes, int n_in,
                              void* d_out, int out_size)
{
    const float* x = (const float*)d_in[0];

    void *p0 = nullptr, *p1 = nullptr;
    cudaGetSymbolAddress(&p0, g_h0);
    cudaGetSymbolAddress(&p1, g_h1);

    const int binBlocks   = DIM * DIM;                   // 9216 lines
    const int slideBlocks = (DIM * DIM * 16) / 256;      // 576

    binx_kernel<<<binBlocks, 256>>>(x, (__half*)p0);                         // x -> Xsum(h0)
    slideY_kernel<<<slideBlocks, 256>>>((const uint2*)p0, (uint2*)p1);       // h0 -> h1
    slideZ_kernel<<<slideBlocks, 256>>>((const uint2*)p1, (float4*)d_out);   // h1 -> out
}